// round 17
// baseline (speedup 1.0000x reference)
#include <cuda_runtime.h>
#include <cstdint>

// ---------------- problem constants ----------------
#define Bsz   64
#define Hsz   1024
#define Dsz   64
#define PBsz  16
#define Tsz   256
#define Gsz   4096          // 4*H
#define K0sz  1104          // (D+PB) + H
#define K0p   1152          // padded to 18*KC
#define K1sz  2048          // H + H  = 32*KC
#define NCTA  128           // persistent CTAs (single wave)
#define NTHR  512           // threads per CTA (16 warps, 4/SMSP)
#define KC    64            // k chunk per cp.async stage (four 16-k quarters)

// ---------------- device scratch ----------------
// Transposed, gate-interleaved weights: WT[k][r], r = 4*unit + gate (i,f,g,o)
__device__ float g_W0T[(size_t)K0p * Gsz];
__device__ float g_W1T[(size_t)K1sz * Gsz];
__device__ float g_X0[2][K0p * Bsz];    // [k][b]; rows 0..63 y, 64..79 pb, 80..1103 h0, pad
__device__ float g_X1[2][K1sz * Bsz];   // rows 0..1023 h0, 1024..2047 h1
__device__ float g_c0[Hsz * Bsz];
__device__ float g_c1[Hsz * Bsz];
__device__ float g_bias0[Gsz];          // bih+bhh, gate-interleaved
__device__ float g_bias1[Gsz];
__device__ unsigned g_bar[Tsz * 3 + 16];

// ---------------- cp.async helpers (memory-clobbered) ----------------
#define CP_ASYNC16(dst, src) \
    asm volatile("cp.async.cg.shared.global [%0], [%1], 16;" :: "r"(dst), "l"(src) : "memory")
#define CP_COMMIT()  asm volatile("cp.async.commit_group;" ::: "memory")
#define CP_WAIT(n)   asm volatile("cp.async.wait_group %0;" :: "n"(n) : "memory")

// ---------------- weight packing (transposed + gate-interleaved + pad) ----------------
__global__ void pack_w0T(const float* __restrict__ Wih, const float* __restrict__ Whh,
                         float* __restrict__ WT) {
    int stride = gridDim.x * blockDim.x;
    for (int i = blockIdx.x * blockDim.x + threadIdx.x; i < K0p * Gsz; i += stride) {
        int r = i & 4095;
        int k = i >> 12;
        int src = (r & 3) * Hsz + (r >> 2);
        float v = 0.f;
        if (k < (Dsz + PBsz))      v = Wih[src * (Dsz + PBsz) + k];
        else if (k < K0sz)         v = Whh[src * Hsz + (k - (Dsz + PBsz))];
        WT[i] = v;
    }
}

__global__ void pack_w1T(const float* __restrict__ Wih, const float* __restrict__ Whh,
                         float* __restrict__ WT) {
    size_t stride = (size_t)gridDim.x * blockDim.x;
    size_t total = (size_t)K1sz * Gsz;
    for (size_t i = (size_t)blockIdx.x * blockDim.x + threadIdx.x; i < total; i += stride) {
        int r = (int)(i & 4095);
        int k = (int)(i >> 12);
        int src = (r & 3) * Hsz + (r >> 2);
        WT[i] = (k < Hsz) ? Wih[(size_t)src * Hsz + k]
                          : Whh[(size_t)src * Hsz + (k - Hsz)];
    }
}

// ---------------- one init kernel ----------------
__global__ void init_state(const int* __restrict__ label, const float* __restrict__ mu_pb,
                           const float* __restrict__ bih0, const float* __restrict__ bhh0,
                           const float* __restrict__ bih1, const float* __restrict__ bhh1) {
    int stride = gridDim.x * blockDim.x;
    int i0 = blockIdx.x * blockDim.x + threadIdx.x;
    float* X0 = &g_X0[0][0];
    for (int i = i0; i < 2 * K0p * Bsz; i += stride) {
        int rem = (i < K0p * Bsz) ? i : i - K0p * Bsz;
        int k = rem >> 6, b = rem & 63;
        float v = 0.f;
        if (k >= Dsz && k < Dsz + PBsz) v = mu_pb[label[b] * PBsz + (k - Dsz)];
        X0[i] = v;
    }
    float* X1 = &g_X1[0][0];
    for (int i = i0; i < 2 * K1sz * Bsz; i += stride) X1[i] = 0.f;
    for (int i = i0; i < Hsz * Bsz; i += stride) { g_c0[i] = 0.f; g_c1[i] = 0.f; }
    for (int i = i0; i < Tsz * 3 + 16; i += stride) g_bar[i] = 0u;
    for (int r = i0; r < Gsz; r += stride) {
        int unit = r >> 2, g = r & 3;
        g_bias0[r] = bih0[g * Hsz + unit] + bhh0[g * Hsz + unit];
        g_bias1[r] = bih1[g * Hsz + unit] + bhh1[g * Hsz + unit];
    }
}

// ---------------- grid barrier ----------------
__device__ __forceinline__ void gsync(unsigned slot) {
    __syncthreads();
    if (threadIdx.x == 0) {
        __threadfence();
        atomicAdd(&g_bar[slot], 1u);
        volatile unsigned* p = &g_bar[slot];
        while (*p < NCTA) { }
        __threadfence();
    }
    __syncthreads();
}

// ---------------- shared layout (dynamic, 81920 B) ----------------
struct Smem {
    float x[2][KC][Bsz];      // 32 KB  staged X chunk, double buffered
    float w[2][KC][32];       // 16 KB  staged W chunk (this CTA's 32 rows)
    float acc[4][Bsz * 32];   // 32 KB  per-kquarter accT[b][r]
};
#define SMEM_BYTES 81920

// ---------------- chunk staging via cp.async (512 threads) ----------------
__device__ __forceinline__ void stage_chunk(Smem* sm, int buf,
        const float* __restrict__ X, const float* __restrict__ Wb, int k0) {
    const int t = threadIdx.x;
    unsigned xd = (unsigned)__cvta_generic_to_shared(&sm->x[buf][0][0]);
    const float* xs = X + (size_t)k0 * Bsz;
#pragma unroll
    for (int j = 0; j < 2; ++j) {
        int i = t + j * NTHR;
        CP_ASYNC16(xd + i * 16, xs + i * 4);
    }
    unsigned wd = (unsigned)__cvta_generic_to_shared(&sm->w[buf][0][0]);
    {
        int i = t;                       // 512 chunks of 16B
        int k = i >> 3, q = i & 7;
        CP_ASYNC16(wd + i * 16, Wb + (size_t)(k0 + k) * Gsz + q * 4);
    }
    CP_COMMIT();
}

// ---------------- fused GEMM + LSTM cell ----------------
// CTA: 32 gate rows (8 units) x 64 batches, in-CTA k-split by 4.
// warp kg = warp>>2 handles k in [kg*16, kg*16+16) of each 64-chunk.
// warp tile: 8 rows x 64 batches (w loads uniform -> broadcast).
// thread tile: 8 rows x 2 batches = 8 FFMA2 per k.
// All smem loads are plain C++ typed loads (ordered vs __syncthreads).
__device__ __forceinline__ void gemm_cell(Smem* sm,
        const float* __restrict__ WT, const float* __restrict__ X, int nch,
        const float* __restrict__ bias,
        float* __restrict__ c, float* __restrict__ h1, float* __restrict__ h2) {
    const int t    = threadIdx.x;
    const int cb   = blockIdx.x;
    const int lane = t & 31, warp = t >> 5;
    const int kg   = warp >> 2;          // k-quarter 0..3
    const int wb   = (warp & 3) * 8;     // 8 rows, uniform across warp
    const int xb   = lane * 2;           // 2 batches, distinct per lane
    const int kq   = kg * 16;            // quarter base within chunk
    const float* Wb = WT + cb * 32;

    // a[rp][j]: rows (wb+2rp, wb+2rp+1), batch xb+j
    unsigned long long a[4][2];
#pragma unroll
    for (int rp = 0; rp < 4; ++rp) { a[rp][0] = 0ull; a[rp][1] = 0ull; }

    stage_chunk(sm, 0, X, Wb, 0);
    for (int ch = 0; ch < nch; ++ch) {
        if (ch + 1 < nch) {
            stage_chunk(sm, (ch + 1) & 1, X, Wb, (ch + 1) * KC);
            CP_WAIT(1);
        } else {
            CP_WAIT(0);
        }
        __syncthreads();

        const int buf = ch & 1;
#pragma unroll
        for (int k = 0; k < 16; ++k) {
            ulonglong2 wA = *reinterpret_cast<const ulonglong2*>(&sm->w[buf][kq + k][wb]);
            ulonglong2 wB = *reinterpret_cast<const ulonglong2*>(&sm->w[buf][kq + k][wb + 4]);
            float2     xv = *reinterpret_cast<const float2*>(&sm->x[buf][kq + k][xb]);
            unsigned long long x0, x1;
            asm("mov.b64 %0, {%1,%1};" : "=l"(x0) : "f"(xv.x));
            asm("mov.b64 %0, {%1,%1};" : "=l"(x1) : "f"(xv.y));
            asm("fma.rn.f32x2 %0, %1, %2, %0;" : "+l"(a[0][0]) : "l"(wA.x), "l"(x0));
            asm("fma.rn.f32x2 %0, %1, %2, %0;" : "+l"(a[0][1]) : "l"(wA.x), "l"(x1));
            asm("fma.rn.f32x2 %0, %1, %2, %0;" : "+l"(a[1][0]) : "l"(wA.y), "l"(x0));
            asm("fma.rn.f32x2 %0, %1, %2, %0;" : "+l"(a[1][1]) : "l"(wA.y), "l"(x1));
            asm("fma.rn.f32x2 %0, %1, %2, %0;" : "+l"(a[2][0]) : "l"(wB.x), "l"(x0));
            asm("fma.rn.f32x2 %0, %1, %2, %0;" : "+l"(a[2][1]) : "l"(wB.x), "l"(x1));
            asm("fma.rn.f32x2 %0, %1, %2, %0;" : "+l"(a[3][0]) : "l"(wB.y), "l"(x0));
            asm("fma.rn.f32x2 %0, %1, %2, %0;" : "+l"(a[3][1]) : "l"(wB.y), "l"(x1));
        }
        __syncthreads();
    }

    // spill accumulators to acc[kg][b][r] (pitch 32)
    {
        float* accT = &sm->acc[kg][0];
        float lo, hi;
#pragma unroll
        for (int rp = 0; rp < 4; ++rp) {
#pragma unroll
            for (int j = 0; j < 2; ++j) {
                asm("mov.b64 {%0,%1}, %2;" : "=f"(lo), "=f"(hi) : "l"(a[rp][j]));
                accT[(xb + j) * 32 + wb + rp * 2 + 0] = lo;
                accT[(xb + j) * 32 + wb + rp * 2 + 1] = hi;
            }
        }
    }
    __syncthreads();

    // fused LSTM cell: 8 units x 64 batches = 512 elems, one per thread
    {
        const int u = t >> 6, b = t & 63;
        const int ju = cb * 8 + u;
        float4 g0 = *reinterpret_cast<const float4*>(&sm->acc[0][b * 32 + u * 4]);
        float4 g1 = *reinterpret_cast<const float4*>(&sm->acc[1][b * 32 + u * 4]);
        float4 g2 = *reinterpret_cast<const float4*>(&sm->acc[2][b * 32 + u * 4]);
        float4 g3 = *reinterpret_cast<const float4*>(&sm->acc[3][b * 32 + u * 4]);
        float4 bb = *reinterpret_cast<const float4*>(&bias[ju * 4]);
        float gi = (g0.x + g1.x) + (g2.x + g3.x) + bb.x;
        float gf = (g0.y + g1.y) + (g2.y + g3.y) + bb.y;
        float gg = (g0.z + g1.z) + (g2.z + g3.z) + bb.z;
        float go = (g0.w + g1.w) + (g2.w + g3.w) + bb.w;
        float si = 1.f / (1.f + expf(-gi));
        float sf = 1.f / (1.f + expf(-gf));
        float so = 1.f / (1.f + expf(-go));
        float cn = sf * c[ju * Bsz + b] + si * tanhf(gg);
        c[ju * Bsz + b] = cn;
        float h = so * tanhf(cn);
        h1[ju * Bsz + b] = h;
        if (h2) h2[ju * Bsz + b] = h;
    }
    __syncthreads();
}

// ---------------- persistent kernel ----------------
__global__ __launch_bounds__(NTHR, 1)
void rnn_persistent(const float* __restrict__ Wlin, const float* __restrict__ blin,
                    float* __restrict__ out) {
    extern __shared__ char smraw[];
    Smem* sm = reinterpret_cast<Smem*>(smraw);
    const int t = threadIdx.x;
    const int cb = blockIdx.x;
    unsigned slot = 0;

    for (int step = 0; step < Tsz; ++step) {
        const int p = step & 1;
        // layer 0: reads X0[p]; h0 -> X1[p] rows [0,1024) and X0[1-p] rows [80,1104)
        gemm_cell(sm, g_W0T, g_X0[p], K0p / KC, g_bias0, g_c0,
                  g_X1[p], g_X0[1 - p] + (Dsz + PBsz) * Bsz);
        gsync(slot++);

        // layer 1: reads X1[p]; h1 -> X1[1-p] rows [1024,2048)
        gemm_cell(sm, g_W1T, g_X1[p], K1sz / KC, g_bias1, g_c1,
                  g_X1[1 - p] + Hsz * Bsz, nullptr);
        gsync(slot++);

        // output linear: CTAs 0..63, one d each; reads h1(t) from X1[1-p]
        if (cb < Dsz) {
            const int d  = cb;
            const int b4 = t & 15;       // 4 batches
            const int js = t >> 4;       // 32 k-slices of 32
            const float* wr  = Wlin + d * Hsz + js * 32;
            const float* h1T = g_X1[1 - p] + (size_t)Hsz * Bsz + (size_t)js * 32 * Bsz;
            float4 a = make_float4(0.f, 0.f, 0.f, 0.f);
#pragma unroll 8
            for (int jj = 0; jj < 32; ++jj) {
                float  w = __ldg(wr + jj);
                float4 x = __ldcg(reinterpret_cast<const float4*>(h1T + (size_t)jj * Bsz) + b4);
                a.x += w * x.x; a.y += w * x.y; a.z += w * x.z; a.w += w * x.w;
            }
            float* lin = &sm->acc[0][0];
            *reinterpret_cast<float4*>(&lin[js * 64 + b4 * 4]) = a;
            __syncthreads();
            if (t < Bsz) {
                float y = blin[d];
#pragma unroll
                for (int j2 = 0; j2 < 32; ++j2) y += lin[j2 * 64 + t];
                out[(size_t)step * Bsz * Dsz + t * Dsz + d] = y;   // outputs[t][b][d]
                g_X0[1 - p][d * Bsz + t] = y;                      // feed back
            }
        }
        gsync(slot++);
    }
}

// ---------------- trailing outputs ----------------
__global__ void extras_kernel(const int* __restrict__ label,
                              const float* __restrict__ mu_pb,
                              const float* __restrict__ logvar_pb,
                              float* __restrict__ out, int out_size) {
    const int base = Tsz * Bsz * Dsz;
    int i = threadIdx.x;
    if (i < Bsz && base + i < out_size) out[base + i] = (float)label[i];
    if (i < Bsz * PBsz) {
        int b = i >> 4, p = i & 15;
        float mv = mu_pb[label[b] * PBsz + p];
        float lv = logvar_pb[label[b] * PBsz + p];
        int o1 = base + Bsz + i;
        int o2 = base + Bsz + Bsz * PBsz + i;
        int o3 = base + Bsz + 2 * Bsz * PBsz + i;
        if (o1 < out_size) out[o1] = mv;
        if (o2 < out_size) out[o2] = mv;
        if (o3 < out_size) out[o3] = lv;
    }
}

// ---------------- host launcher ----------------
extern "C" void kernel_launch(void* const* d_in, const int* in_sizes, int n_in,
                              void* d_out, int out_size) {
    int o = 0;
    const int*   label = (const int*)d_in[o++];
    if (o < n_in && in_sizes[o] == 1) o++;             // forward_computation_length
    const float* mu_pb     = (const float*)d_in[o++];
    const float* logvar_pb = (const float*)d_in[o++];
    const float* Wih0 = (const float*)d_in[o++];
    const float* Whh0 = (const float*)d_in[o++];
    const float* bih0 = (const float*)d_in[o++];
    const float* bhh0 = (const float*)d_in[o++];
    const float* Wih1 = (const float*)d_in[o++];
    const float* Whh1 = (const float*)d_in[o++];
    const float* bih1 = (const float*)d_in[o++];
    const float* bhh1 = (const float*)d_in[o++];
    const float* Wlin = (const float*)d_in[o++];
    const float* blin = (const float*)d_in[o++];
    float* out = (float*)d_out;

    float *W0T, *W1T;
    cudaGetSymbolAddress((void**)&W0T, g_W0T);
    cudaGetSymbolAddress((void**)&W1T, g_W1T);

    cudaFuncSetAttribute(rnn_persistent,
                         cudaFuncAttributeMaxDynamicSharedMemorySize, SMEM_BYTES);

    pack_w0T<<<2048, 256>>>(Wih0, Whh0, W0T);
    pack_w1T<<<2048, 256>>>(Wih1, Whh1, W1T);
    init_state<<<512, 256>>>(label, mu_pb, bih0, bhh0, bih1, bhh1);
    rnn_persistent<<<NCTA, NTHR, SMEM_BYTES>>>(Wlin, blin, out);

    if (out_size > Tsz * Bsz * Dsz)
        extras_kernel<<<1, 1024>>>(label, mu_pb, logvar_pb, out, out_size);
}